// round 11
// baseline (speedup 1.0000x reference)
#include <cuda_runtime.h>
#include <cuda_bf16.h>
#include <cstdint>

#define KS   5
#define K2   25
#define C1   32
#define C2   64
#define NG   64
#define NMAX 20000
#define EMAX 320000
#define KTOT 800

// ---------------- scratch (device globals; no allocations) ----------------
__device__ float        g_T[NMAX * K2];
__device__ float        g_deg[NMAX];
__device__ float        g_dinv[NMAX];
__device__ unsigned int g_h1b[NMAX * 16];     // h1 bf16x2 packed [N][16]
__device__ unsigned int g_Sb[NMAX * 400];     // S accum bf16x2 [N][25][16] (32MB), pre-scaled by dinv[dst]
__device__ uint2        g_W2f[56 * 8 * 32];   // B fragments: [kstep][ngroup][lane] (+root2 at 52-53)
__device__ float        g_pool[NG * C2];
__device__ float4       g_bwp[EMAX];          // per-edge fp32 basis weights (edge1 -> rec)
__device__ uint4        g_rec[EMAX];          // per-edge record: {src|wi0<<20, dst, bw01*dinv bf16x2, bw23*dinv bf16x2}

// ---------------- helpers ----------------
__device__ __forceinline__ uint32_t smem_u32(const void* p) {
    uint32_t a;
    asm("{ .reg .u64 t; cvta.to.shared.u64 t, %1; cvt.u32.u64 %0, t; }" : "=r"(a) : "l"(p));
    return a;
}
__device__ __forceinline__ void red_bf162(unsigned int* addr, unsigned int v) {
    asm volatile("red.global.add.noftz.bf16x2 [%0], %1;" :: "l"(addr), "r"(v) : "memory");
}
__device__ __forceinline__ void red_f32(float* addr, float v) {
    asm volatile("red.global.add.f32 [%0], %1;" :: "l"(addr), "f"(v) : "memory");
}
__device__ __forceinline__ void ldmatrix_x4(uint32_t& a0, uint32_t& a1, uint32_t& a2,
                                            uint32_t& a3, uint32_t addr) {
    asm volatile("ldmatrix.sync.aligned.m8n8.x4.shared.b16 {%0,%1,%2,%3}, [%4];"
                 : "=r"(a0), "=r"(a1), "=r"(a2), "=r"(a3) : "r"(addr));
}
__device__ __forceinline__ void mma_bf16(float* c, uint32_t a0, uint32_t a1, uint32_t a2,
                                         uint32_t a3, uint32_t b0, uint32_t b1) {
    asm volatile(
        "mma.sync.aligned.m16n8k16.row.col.f32.bf16.bf16.f32 "
        "{%0,%1,%2,%3}, {%4,%5,%6,%7}, {%8,%9}, {%0,%1,%2,%3};"
        : "+f"(c[0]), "+f"(c[1]), "+f"(c[2]), "+f"(c[3])
        : "r"(a0), "r"(a1), "r"(a2), "r"(a3), "r"(b0), "r"(b1));
}

// ---------------- basis (wi0 form: indices are wi0, +1, +5, +6) ----------------
__device__ __forceinline__ void basis2w(float a0, float a1, int& wi0, float* bw) {
    float v0 = a0 * (KS - 1), v1 = a1 * (KS - 1);
    int k0 = (int)floorf(v0); k0 = min(max(k0, 0), KS - 2);
    int k1 = (int)floorf(v1); k1 = min(max(k1, 0), KS - 2);
    float f0 = v0 - (float)k0, f1 = v1 - (float)k1;
    float g0 = 1.f - f0, g1 = 1.f - f1;
    wi0 = k0 + KS * k1;
    bw[0] = g0 * g1;  // wi0
    bw[1] = f0 * g1;  // wi0+1
    bw[2] = g0 * f1;  // wi0+5
    bw[3] = f0 * f1;  // wi0+6
}

// ---------------- zero scratch + prep B fragments (fused) ----------------
__global__ void k_zero_prep(const float* __restrict__ W2, const float* __restrict__ root2,
                            int N) {
    long tid = (long)blockIdx.x * blockDim.x + threadIdx.x;
    long stride = (long)gridDim.x * blockDim.x;
    long nS4 = (long)N * 100;
    uint4* S4 = (uint4*)g_Sb;
    uint4 z4 = make_uint4(0u, 0u, 0u, 0u);
    for (long i = tid; i < nS4; i += stride) S4[i] = z4;
    long nT = (long)N * K2;
    for (long i = tid; i < nT; i += stride) g_T[i] = 0.f;
    for (long i = tid; i < N; i += stride) g_deg[i] = 0.f;
    for (long i = tid; i < NG * C2; i += stride) g_pool[i] = 0.f;
    if (tid < 56 * 8 * 32) {
        int t = (int)tid;
        int lane = t & 31, ng = (t >> 5) & 7, sg = t >> 8;
        int gid = lane >> 2, tig = lane & 3;
        int n = ng * 8 + gid;
        int k = sg * 16 + tig * 2;
        float f0 = 0.f, f1 = 0.f, f2 = 0.f, f3 = 0.f;
        if (sg < 50) {
            f0 = W2[k * C2 + n];       f1 = W2[(k + 1) * C2 + n];
            f2 = W2[(k + 8) * C2 + n]; f3 = W2[(k + 9) * C2 + n];
        } else if (sg >= 52 && sg < 54) {
            int kr = k - 832;
            f0 = root2[kr * C2 + n];       f1 = root2[(kr + 1) * C2 + n];
            f2 = root2[(kr + 8) * C2 + n]; f3 = root2[(kr + 9) * C2 + n];
        }
        __nv_bfloat162 lo = __float22bfloat162_rn(make_float2(f0, f1));
        __nv_bfloat162 hi = __float22bfloat162_rn(make_float2(f2, f3));
        g_W2f[t] = make_uint2(*(uint32_t*)&lo, *(uint32_t*)&hi);
    }
}

// ---------------- edge pass 1 (stores src|wi0, dst into record; fp32 bw aside) ----------------
__global__ void k_edge1(const float* __restrict__ x, const float* __restrict__ ea,
                        const int* __restrict__ src, const int* __restrict__ dst, int E) {
    int e = blockIdx.x * blockDim.x + threadIdx.x;
    if (e >= E) return;
    int wi0; float bw[4];
    float2 eav = ((const float2*)ea)[e];
    basis2w(eav.x, eav.y, wi0, bw);
    int s = src[e];
    float xs = x[s];
    int d = dst[e];
    float* Tp = g_T + d * K2 + wi0;
    atomicAdd(Tp,     bw[0] * xs);
    atomicAdd(Tp + 1, bw[1] * xs);
    atomicAdd(Tp + 5, bw[2] * xs);
    atomicAdd(Tp + 6, bw[3] * xs);
    atomicAdd(g_deg + d, 1.f);
    *(uint2*)&g_rec[e] = make_uint2((uint32_t)s | ((uint32_t)wi0 << 20), (uint32_t)d);
    g_bwp[e] = make_float4(bw[0], bw[1], bw[2], bw[3]);
}

// ---------------- layer-1 node update (per-thread form, atomic-free) ----------------
__global__ void k_h1(const float* __restrict__ x, const float* __restrict__ W1,
                     const float* __restrict__ root1, const float* __restrict__ b1, int N) {
    int t = blockIdx.x * blockDim.x + threadIdx.x;
    if (t >= N * 16) return;
    int n = t >> 4, c2 = t & 15;
    const float* Tp = g_T + n * K2;
    float a0 = 0.f, a1 = 0.f;
#pragma unroll
    for (int w = 0; w < K2; w++) {
        float tv = Tp[w];
        a0 += tv * W1[w * C1 + 2 * c2];
        a1 += tv * W1[w * C1 + 2 * c2 + 1];
    }
    float dinv = 1.f / fmaxf(g_deg[n], 1.f);
    float xn = x[n];
    float h0 = fmaxf(a0 * dinv + xn * root1[2 * c2]     + b1[2 * c2],     0.f);
    float h1 = fmaxf(a1 * dinv + xn * root1[2 * c2 + 1] + b1[2 * c2 + 1], 0.f);
    __nv_bfloat162 hb = __float22bfloat162_rn(make_float2(h0, h1));
    g_h1b[t] = *(unsigned int*)&hb;
    if (c2 == 0) g_dinv[n] = dinv;
}

// ---------------- record finalize: fold dinv[dst] into bw, pack bf16 ----------------
__global__ void k_rec(int E) {
    int e = blockIdx.x * blockDim.x + threadIdx.x;
    if (e >= E) return;
    uint2 ab = *(const uint2*)&g_rec[e];
    float4 bw = g_bwp[e];
    float dinv = g_dinv[ab.y];
    __nv_bfloat162 c01 = __float22bfloat162_rn(make_float2(bw.x * dinv, bw.y * dinv));
    __nv_bfloat162 c23 = __float22bfloat162_rn(make_float2(bw.z * dinv, bw.w * dinv));
    *(uint2*)((uint32_t*)&g_rec[e] + 2) = make_uint2(*(uint32_t*)&c01, *(uint32_t*)&c23);
}

// ---------------- edge pass 2: 16 lanes/edge, single 16B record load ----------------
__global__ void k_edge2(int E) {
    int gt = blockIdx.x * blockDim.x + threadIdx.x;
    int lane = gt & 31;
    int warp = gt >> 5;
    int e = warp * 2 + (lane >> 4);
    int hl = lane & 15;
    if (e >= E) return;
    uint4 r = g_rec[e];
    int s   = (int)(r.x & 0xFFFFFu);
    int wi0 = (int)(r.x >> 20);
    int d   = (int)r.y;
    float2 bw01 = __bfloat1622float2(*(__nv_bfloat162*)&r.z);
    float2 bw23 = __bfloat1622float2(*(__nv_bfloat162*)&r.w);
    float2 h = __bfloat1622float2(*(__nv_bfloat162*)&g_h1b[s * 16 + hl]);
    unsigned int* base = g_Sb + d * 400 + wi0 * 16 + hl;
    {
        __nv_bfloat162 v = __float22bfloat162_rn(make_float2(bw01.x * h.x, bw01.x * h.y));
        red_bf162(base, *(unsigned int*)&v);
    }
    {
        __nv_bfloat162 v = __float22bfloat162_rn(make_float2(bw01.y * h.x, bw01.y * h.y));
        red_bf162(base + 16, *(unsigned int*)&v);
    }
    {
        __nv_bfloat162 v = __float22bfloat162_rn(make_float2(bw23.x * h.x, bw23.x * h.y));
        red_bf162(base + 80, *(unsigned int*)&v);
    }
    {
        __nv_bfloat162 v = __float22bfloat162_rn(make_float2(bw23.y * h.x, bw23.y * h.y));
        red_bf162(base + 96, *(unsigned int*)&v);
    }
}

// ---------------- fused GEMM (HMMA) + layer-2 epilogue + pooling ----------------
__global__ void __launch_bounds__(256) k_gemm_mma(const float* __restrict__ b2,
                                                  const int* __restrict__ batch, int N) {
    __shared__ __align__(16) uint8_t smA[16384];
    int tid = threadIdx.x;
    int warp = tid >> 5, lane = tid & 31;
    int gid = lane >> 2, tig = lane & 3;
    int rowBase = blockIdx.x * 128;
    uint32_t smA_b = smem_u32(smA);

    int rowA[4], chA[4], stoff[4];
    bool inb[4];
#pragma unroll
    for (int j = 0; j < 4; j++) {
        int c = tid + 256 * j;
        rowA[j] = c >> 3; chA[j] = c & 7;
        stoff[j] = rowA[j] * 128 + ((chA[j] ^ (rowA[j] & 7)) << 4);
        inb[j] = (rowBase + rowA[j]) < N;
    }

    float acc[8][4];
#pragma unroll
    for (int g = 0; g < 8; g++)
#pragma unroll
        for (int j = 0; j < 4; j++) acc[g][j] = 0.f;

    uint4 v[4];
#pragma unroll
    for (int j = 0; j < 4; j++) {
        v[j] = make_uint4(0u, 0u, 0u, 0u);
        if (inb[j])
            v[j] = *(const uint4*)(g_Sb + (rowBase + rowA[j]) * 400 + chA[j] * 4);
    }

    for (int c0 = 0; c0 < 14; c0++) {
#pragma unroll
        for (int j = 0; j < 4; j++) *(uint4*)(smA + stoff[j]) = v[j];
        __syncthreads();
        if (c0 < 13) {
            int cn = c0 + 1;
#pragma unroll
            for (int j = 0; j < 4; j++) {
                v[j] = make_uint4(0u, 0u, 0u, 0u);
                if (inb[j]) {
                    if (cn < 13) {
                        int off = cn * 32 + chA[j] * 4;
                        if (off < 400)
                            v[j] = *(const uint4*)(g_Sb + (rowBase + rowA[j]) * 400 + off);
                    } else if (chA[j] < 4) {
                        v[j] = *(const uint4*)(g_h1b + (rowBase + rowA[j]) * 16 + chA[j] * 4);
                    }
                }
            }
        }
#pragma unroll
        for (int ks = 0; ks < 4; ks++) {
            int mrow = warp * 16 + (lane & 15);
            uint32_t addr = smA_b + mrow * 128 + (((ks * 2 + (lane >> 4)) ^ (mrow & 7)) << 4);
            uint32_t a0, a1, a2, a3;
            ldmatrix_x4(a0, a1, a2, a3, addr);
            int sg = c0 * 4 + ks;
            const uint2* bf = g_W2f + (sg << 8) + lane;
#pragma unroll
            for (int ng = 0; ng < 8; ng++) {
                uint2 b = bf[ng << 5];
                mma_bf16(acc[ng], a0, a1, a2, a3, b.x, b.y);
            }
        }
        __syncthreads();
    }

    int r0 = rowBase + warp * 16 + gid;
    int r1 = r0 + 8;
    int bt0 = (r0 < N) ? batch[r0] : -1;
    int bt1 = (r1 < N) ? batch[r1] : -1;
#pragma unroll
    for (int ng = 0; ng < 8; ng++) {
        int col = ng * 8 + tig * 2;
        float2 bb = *(const float2*)(b2 + col);
        if (bt0 >= 0) {
            red_f32(g_pool + bt0 * C2 + col,     fmaxf(acc[ng][0] + bb.x, 0.f));
            red_f32(g_pool + bt0 * C2 + col + 1, fmaxf(acc[ng][1] + bb.y, 0.f));
        }
        if (bt1 >= 0) {
            red_f32(g_pool + bt1 * C2 + col,     fmaxf(acc[ng][2] + bb.x, 0.f));
            red_f32(g_pool + bt1 * C2 + col + 1, fmaxf(acc[ng][3] + bb.y, 0.f));
        }
    }
}

// ---------------- head MLP + log_softmax (cnt via binary search on sorted batch) ----------------
__global__ void k_mlp(const float* __restrict__ Wf1, const float* __restrict__ bf1,
                      const float* __restrict__ Wf2, const float* __restrict__ bf2,
                      const int* __restrict__ batch, int N,
                      float* __restrict__ out) {
    int b = blockIdx.x;
    int j = threadIdx.x;
    __shared__ float gs[C2];
    __shared__ float ts[128];
    __shared__ float lg[10];
    __shared__ float s_cinv;
    if (j == 0) {
        int lo = 0, hi = N;
        while (lo < hi) { int m = (lo + hi) >> 1; if (batch[m] < b) lo = m + 1; else hi = m; }
        int lo2 = lo; hi = N;
        while (lo2 < hi) { int m = (lo2 + hi) >> 1; if (batch[m] < b + 1) lo2 = m + 1; else hi = m; }
        s_cinv = 1.f / fmaxf((float)(lo2 - lo), 1.f);
    }
    __syncthreads();
    if (j < C2) gs[j] = g_pool[b * C2 + j] * s_cinv;
    __syncthreads();
    float t = bf1[j];
#pragma unroll
    for (int k = 0; k < C2; k++) t += gs[k] * Wf1[k * 128 + j];
    ts[j] = fmaxf(t, 0.f);
    __syncthreads();
    if (j < 10) {
        float a = bf2[j];
#pragma unroll
        for (int q = 0; q < 128; q++) a += ts[q] * Wf2[q * 10 + j];
        lg[j] = a;
    }
    __syncthreads();
    if (j == 0) {
        float m = lg[0];
#pragma unroll
        for (int q = 1; q < 10; q++) m = fmaxf(m, lg[q]);
        float s = 0.f;
#pragma unroll
        for (int q = 0; q < 10; q++) s += expf(lg[q] - m);
        float l = logf(s) + m;
#pragma unroll
        for (int q = 0; q < 10; q++) out[b * 10 + q] = lg[q] - l;
    }
}

// ---------------- launch ----------------
extern "C" void kernel_launch(void* const* d_in, const int* in_sizes, int n_in,
                              void* d_out, int out_size) {
    const float* x     = (const float*)d_in[0];
    const float* ea    = (const float*)d_in[1];
    const float* W1    = (const float*)d_in[2];
    const float* root1 = (const float*)d_in[3];
    const float* b1    = (const float*)d_in[4];
    const float* W2    = (const float*)d_in[5];
    const float* root2 = (const float*)d_in[6];
    const float* b2    = (const float*)d_in[7];
    const float* Wf1   = (const float*)d_in[8];
    const float* bf1   = (const float*)d_in[9];
    const float* Wf2   = (const float*)d_in[10];
    const float* bf2   = (const float*)d_in[11];
    const int*   ei    = (const int*)d_in[12];
    const int*   batch = (const int*)d_in[13];

    int N = in_sizes[0];
    int E = in_sizes[1] / 2;
    const int* src = ei;
    const int* dst = ei + E;
    float* out = (float*)d_out;

    k_zero_prep<<<2048, 256>>>(W2, root2, N);
    k_edge1<<<(E + 255) / 256, 256>>>(x, ea, src, dst, E);
    k_h1<<<(N * 16 + 255) / 256, 256>>>(x, W1, root1, b1, N);
    k_rec<<<(E + 255) / 256, 256>>>(E);
    k_edge2<<<(E * 16 + 255) / 256, 256>>>(E);
    k_gemm_mma<<<(N + 127) / 128, 256>>>(b2, batch, N);
    k_mlp<<<NG, 128>>>(Wf1, bf1, Wf2, bf2, batch, N, out);
}

// round 12
// speedup vs baseline: 1.0218x; 1.0218x over previous
#include <cuda_runtime.h>
#include <cuda_bf16.h>
#include <cstdint>

#define KS   5
#define K2   25
#define C1   32
#define C2   64
#define NG   64
#define NMAX 20000
#define EMAX 320000
#define KTOT 800

// ---------------- scratch (device globals; no allocations) ----------------
__device__ float        g_T[NMAX * K2];
__device__ float        g_deg[NMAX];
__device__ float        g_dinv[NMAX];
__device__ unsigned int g_h1b[NMAX * 16];     // h1 bf16x2 packed [N][16]
__device__ unsigned int g_Sb[NMAX * 400];     // S accum bf16x2 [N][25][16] (32MB), pre-scaled by dinv[dst]
__device__ uint2        g_W2f[56 * 8 * 32];   // B fragments: [kstep][ngroup][lane] (+root2 at 52-53)
__device__ float        g_pool[NG * C2];
__device__ uint4        g_rec[EMAX];          // per-edge record: {src|wi0<<20, dst, bw01 bf16x2, bw23 bf16x2}

// ---------------- helpers ----------------
__device__ __forceinline__ uint32_t smem_u32(const void* p) {
    uint32_t a;
    asm("{ .reg .u64 t; cvta.to.shared.u64 t, %1; cvt.u32.u64 %0, t; }" : "=r"(a) : "l"(p));
    return a;
}
__device__ __forceinline__ void red_bf162(unsigned int* addr, unsigned int v) {
    asm volatile("red.global.add.noftz.bf16x2 [%0], %1;" :: "l"(addr), "r"(v) : "memory");
}
__device__ __forceinline__ void red_f32(float* addr, float v) {
    asm volatile("red.global.add.f32 [%0], %1;" :: "l"(addr), "f"(v) : "memory");
}
__device__ __forceinline__ void ldmatrix_x4(uint32_t& a0, uint32_t& a1, uint32_t& a2,
                                            uint32_t& a3, uint32_t addr) {
    asm volatile("ldmatrix.sync.aligned.m8n8.x4.shared.b16 {%0,%1,%2,%3}, [%4];"
                 : "=r"(a0), "=r"(a1), "=r"(a2), "=r"(a3) : "r"(addr));
}
__device__ __forceinline__ void mma_bf16(float* c, uint32_t a0, uint32_t a1, uint32_t a2,
                                         uint32_t a3, uint32_t b0, uint32_t b1) {
    asm volatile(
        "mma.sync.aligned.m16n8k16.row.col.f32.bf16.bf16.f32 "
        "{%0,%1,%2,%3}, {%4,%5,%6,%7}, {%8,%9}, {%0,%1,%2,%3};"
        : "+f"(c[0]), "+f"(c[1]), "+f"(c[2]), "+f"(c[3])
        : "r"(a0), "r"(a1), "r"(a2), "r"(a3), "r"(b0), "r"(b1));
}

// ---------------- basis (wi0 form: indices are wi0, +1, +5, +6) ----------------
__device__ __forceinline__ void basis2w(float a0, float a1, int& wi0, float* bw) {
    float v0 = a0 * (KS - 1), v1 = a1 * (KS - 1);
    int k0 = (int)floorf(v0); k0 = min(max(k0, 0), KS - 2);
    int k1 = (int)floorf(v1); k1 = min(max(k1, 0), KS - 2);
    float f0 = v0 - (float)k0, f1 = v1 - (float)k1;
    float g0 = 1.f - f0, g1 = 1.f - f1;
    wi0 = k0 + KS * k1;
    bw[0] = g0 * g1;  // wi0
    bw[1] = f0 * g1;  // wi0+1
    bw[2] = g0 * f1;  // wi0+5
    bw[3] = f0 * f1;  // wi0+6
}

// ---------------- zero scratch + prep B fragments (fused) ----------------
__global__ void k_zero_prep(const float* __restrict__ W2, const float* __restrict__ root2,
                            int N) {
    long tid = (long)blockIdx.x * blockDim.x + threadIdx.x;
    long stride = (long)gridDim.x * blockDim.x;
    long nS4 = (long)N * 100;
    uint4* S4 = (uint4*)g_Sb;
    uint4 z4 = make_uint4(0u, 0u, 0u, 0u);
    for (long i = tid; i < nS4; i += stride) S4[i] = z4;
    long nT = (long)N * K2;
    for (long i = tid; i < nT; i += stride) g_T[i] = 0.f;
    for (long i = tid; i < N; i += stride) g_deg[i] = 0.f;
    for (long i = tid; i < NG * C2; i += stride) g_pool[i] = 0.f;
    if (tid < 56 * 8 * 32) {
        int t = (int)tid;
        int lane = t & 31, ng = (t >> 5) & 7, sg = t >> 8;
        int gid = lane >> 2, tig = lane & 3;
        int n = ng * 8 + gid;
        int k = sg * 16 + tig * 2;
        float f0 = 0.f, f1 = 0.f, f2 = 0.f, f3 = 0.f;
        if (sg < 50) {
            f0 = W2[k * C2 + n];       f1 = W2[(k + 1) * C2 + n];
            f2 = W2[(k + 8) * C2 + n]; f3 = W2[(k + 9) * C2 + n];
        } else if (sg >= 52 && sg < 54) {
            int kr = k - 832;
            f0 = root2[kr * C2 + n];       f1 = root2[(kr + 1) * C2 + n];
            f2 = root2[(kr + 8) * C2 + n]; f3 = root2[(kr + 9) * C2 + n];
        }
        __nv_bfloat162 lo = __float22bfloat162_rn(make_float2(f0, f1));
        __nv_bfloat162 hi = __float22bfloat162_rn(make_float2(f2, f3));
        g_W2f[t] = make_uint2(*(uint32_t*)&lo, *(uint32_t*)&hi);
    }
}

// ---------------- edge pass 1 (builds the complete 16B record inline) ----------------
__global__ void k_edge1(const float* __restrict__ x, const float* __restrict__ ea,
                        const int* __restrict__ src, const int* __restrict__ dst, int E) {
    int e = blockIdx.x * blockDim.x + threadIdx.x;
    if (e >= E) return;
    int wi0; float bw[4];
    float2 eav = ((const float2*)ea)[e];
    basis2w(eav.x, eav.y, wi0, bw);
    int s = src[e];
    float xs = x[s];
    int d = dst[e];
    float* Tp = g_T + d * K2 + wi0;
    atomicAdd(Tp,     bw[0] * xs);
    atomicAdd(Tp + 1, bw[1] * xs);
    atomicAdd(Tp + 5, bw[2] * xs);
    atomicAdd(Tp + 6, bw[3] * xs);
    atomicAdd(g_deg + d, 1.f);
    __nv_bfloat162 c01 = __float22bfloat162_rn(make_float2(bw[0], bw[1]));
    __nv_bfloat162 c23 = __float22bfloat162_rn(make_float2(bw[2], bw[3]));
    g_rec[e] = make_uint4((uint32_t)s | ((uint32_t)wi0 << 20), (uint32_t)d,
                          *(uint32_t*)&c01, *(uint32_t*)&c23);
}

// ---------------- layer-1 node update (per-thread form, atomic-free) ----------------
__global__ void k_h1(const float* __restrict__ x, const float* __restrict__ W1,
                     const float* __restrict__ root1, const float* __restrict__ b1, int N) {
    int t = blockIdx.x * blockDim.x + threadIdx.x;
    if (t >= N * 16) return;
    int n = t >> 4, c2 = t & 15;
    const float* Tp = g_T + n * K2;
    float a0 = 0.f, a1 = 0.f;
#pragma unroll
    for (int w = 0; w < K2; w++) {
        float tv = Tp[w];
        a0 += tv * W1[w * C1 + 2 * c2];
        a1 += tv * W1[w * C1 + 2 * c2 + 1];
    }
    float dinv = 1.f / fmaxf(g_deg[n], 1.f);
    float xn = x[n];
    float h0 = fmaxf(a0 * dinv + xn * root1[2 * c2]     + b1[2 * c2],     0.f);
    float h1 = fmaxf(a1 * dinv + xn * root1[2 * c2 + 1] + b1[2 * c2 + 1], 0.f);
    __nv_bfloat162 hb = __float22bfloat162_rn(make_float2(h0, h1));
    g_h1b[t] = *(unsigned int*)&hb;
    if (c2 == 0) g_dinv[n] = dinv;
}

// ---------------- edge pass 2: 16 lanes/edge, 16B record + dinv + h1 gather ----------------
__global__ void k_edge2(int E) {
    int gt = blockIdx.x * blockDim.x + threadIdx.x;
    int lane = gt & 31;
    int warp = gt >> 5;
    int e = warp * 2 + (lane >> 4);
    int hl = lane & 15;
    if (e >= E) return;
    uint4 r = g_rec[e];
    int s   = (int)(r.x & 0xFFFFFu);
    int wi0 = (int)(r.x >> 20);
    int d   = (int)r.y;
    float2 bw01 = __bfloat1622float2(*(__nv_bfloat162*)&r.z);
    float2 bw23 = __bfloat1622float2(*(__nv_bfloat162*)&r.w);
    float dinv = g_dinv[d];
    float2 h = __bfloat1622float2(*(__nv_bfloat162*)&g_h1b[s * 16 + hl]);
    h.x *= dinv; h.y *= dinv;
    unsigned int* base = g_Sb + d * 400 + wi0 * 16 + hl;
    {
        __nv_bfloat162 v = __float22bfloat162_rn(make_float2(bw01.x * h.x, bw01.x * h.y));
        red_bf162(base, *(unsigned int*)&v);
    }
    {
        __nv_bfloat162 v = __float22bfloat162_rn(make_float2(bw01.y * h.x, bw01.y * h.y));
        red_bf162(base + 16, *(unsigned int*)&v);
    }
    {
        __nv_bfloat162 v = __float22bfloat162_rn(make_float2(bw23.x * h.x, bw23.x * h.y));
        red_bf162(base + 80, *(unsigned int*)&v);
    }
    {
        __nv_bfloat162 v = __float22bfloat162_rn(make_float2(bw23.y * h.x, bw23.y * h.y));
        red_bf162(base + 96, *(unsigned int*)&v);
    }
}

// ---------------- fused GEMM (HMMA) + layer-2 epilogue + pooling ----------------
__global__ void __launch_bounds__(256) k_gemm_mma(const float* __restrict__ b2,
                                                  const int* __restrict__ batch, int N) {
    __shared__ __align__(16) uint8_t smA[16384];
    int tid = threadIdx.x;
    int warp = tid >> 5, lane = tid & 31;
    int gid = lane >> 2, tig = lane & 3;
    int rowBase = blockIdx.x * 128;
    uint32_t smA_b = smem_u32(smA);

    int rowA[4], chA[4], stoff[4];
    bool inb[4];
#pragma unroll
    for (int j = 0; j < 4; j++) {
        int c = tid + 256 * j;
        rowA[j] = c >> 3; chA[j] = c & 7;
        stoff[j] = rowA[j] * 128 + ((chA[j] ^ (rowA[j] & 7)) << 4);
        inb[j] = (rowBase + rowA[j]) < N;
    }

    float acc[8][4];
#pragma unroll
    for (int g = 0; g < 8; g++)
#pragma unroll
        for (int j = 0; j < 4; j++) acc[g][j] = 0.f;

    uint4 v[4];
#pragma unroll
    for (int j = 0; j < 4; j++) {
        v[j] = make_uint4(0u, 0u, 0u, 0u);
        if (inb[j])
            v[j] = *(const uint4*)(g_Sb + (rowBase + rowA[j]) * 400 + chA[j] * 4);
    }

    for (int c0 = 0; c0 < 14; c0++) {
#pragma unroll
        for (int j = 0; j < 4; j++) *(uint4*)(smA + stoff[j]) = v[j];
        __syncthreads();
        if (c0 < 13) {
            int cn = c0 + 1;
#pragma unroll
            for (int j = 0; j < 4; j++) {
                v[j] = make_uint4(0u, 0u, 0u, 0u);
                if (inb[j]) {
                    if (cn < 13) {
                        int off = cn * 32 + chA[j] * 4;
                        if (off < 400)
                            v[j] = *(const uint4*)(g_Sb + (rowBase + rowA[j]) * 400 + off);
                    } else if (chA[j] < 4) {
                        v[j] = *(const uint4*)(g_h1b + (rowBase + rowA[j]) * 16 + chA[j] * 4);
                    }
                }
            }
        }
#pragma unroll
        for (int ks = 0; ks < 4; ks++) {
            int mrow = warp * 16 + (lane & 15);
            uint32_t addr = smA_b + mrow * 128 + (((ks * 2 + (lane >> 4)) ^ (mrow & 7)) << 4);
            uint32_t a0, a1, a2, a3;
            ldmatrix_x4(a0, a1, a2, a3, addr);
            int sg = c0 * 4 + ks;
            const uint2* bf = g_W2f + (sg << 8) + lane;
#pragma unroll
            for (int ng = 0; ng < 8; ng++) {
                uint2 b = bf[ng << 5];
                mma_bf16(acc[ng], a0, a1, a2, a3, b.x, b.y);
            }
        }
        __syncthreads();
    }

    int r0 = rowBase + warp * 16 + gid;
    int r1 = r0 + 8;
    int bt0 = (r0 < N) ? batch[r0] : -1;
    int bt1 = (r1 < N) ? batch[r1] : -1;
#pragma unroll
    for (int ng = 0; ng < 8; ng++) {
        int col = ng * 8 + tig * 2;
        float2 bb = *(const float2*)(b2 + col);
        if (bt0 >= 0) {
            red_f32(g_pool + bt0 * C2 + col,     fmaxf(acc[ng][0] + bb.x, 0.f));
            red_f32(g_pool + bt0 * C2 + col + 1, fmaxf(acc[ng][1] + bb.y, 0.f));
        }
        if (bt1 >= 0) {
            red_f32(g_pool + bt1 * C2 + col,     fmaxf(acc[ng][2] + bb.x, 0.f));
            red_f32(g_pool + bt1 * C2 + col + 1, fmaxf(acc[ng][3] + bb.y, 0.f));
        }
    }
}

// ---------------- head MLP + log_softmax (cnt via binary search on sorted batch) ----------------
__global__ void k_mlp(const float* __restrict__ Wf1, const float* __restrict__ bf1,
                      const float* __restrict__ Wf2, const float* __restrict__ bf2,
                      const int* __restrict__ batch, int N,
                      float* __restrict__ out) {
    int b = blockIdx.x;
    int j = threadIdx.x;
    __shared__ float gs[C2];
    __shared__ float ts[128];
    __shared__ float lg[10];
    __shared__ float s_cinv;
    if (j == 0) {
        int lo = 0, hi = N;
        while (lo < hi) { int m = (lo + hi) >> 1; if (batch[m] < b) lo = m + 1; else hi = m; }
        int lo2 = lo; hi = N;
        while (lo2 < hi) { int m = (lo2 + hi) >> 1; if (batch[m] < b + 1) lo2 = m + 1; else hi = m; }
        s_cinv = 1.f / fmaxf((float)(lo2 - lo), 1.f);
    }
    __syncthreads();
    if (j < C2) gs[j] = g_pool[b * C2 + j] * s_cinv;
    __syncthreads();
    float t = bf1[j];
#pragma unroll
    for (int k = 0; k < C2; k++) t += gs[k] * Wf1[k * 128 + j];
    ts[j] = fmaxf(t, 0.f);
    __syncthreads();
    if (j < 10) {
        float a = bf2[j];
#pragma unroll
        for (int q = 0; q < 128; q++) a += ts[q] * Wf2[q * 10 + j];
        lg[j] = a;
    }
    __syncthreads();
    if (j == 0) {
        float m = lg[0];
#pragma unroll
        for (int q = 1; q < 10; q++) m = fmaxf(m, lg[q]);
        float s = 0.f;
#pragma unroll
        for (int q = 0; q < 10; q++) s += expf(lg[q] - m);
        float l = logf(s) + m;
#pragma unroll
        for (int q = 0; q < 10; q++) out[b * 10 + q] = lg[q] - l;
    }
}

// ---------------- launch ----------------
extern "C" void kernel_launch(void* const* d_in, const int* in_sizes, int n_in,
                              void* d_out, int out_size) {
    const float* x     = (const float*)d_in[0];
    const float* ea    = (const float*)d_in[1];
    const float* W1    = (const float*)d_in[2];
    const float* root1 = (const float*)d_in[3];
    const float* b1    = (const float*)d_in[4];
    const float* W2    = (const float*)d_in[5];
    const float* root2 = (const float*)d_in[6];
    const float* b2    = (const float*)d_in[7];
    const float* Wf1   = (const float*)d_in[8];
    const float* bf1   = (const float*)d_in[9];
    const float* Wf2   = (const float*)d_in[10];
    const float* bf2   = (const float*)d_in[11];
    const int*   ei    = (const int*)d_in[12];
    const int*   batch = (const int*)d_in[13];

    int N = in_sizes[0];
    int E = in_sizes[1] / 2;
    const int* src = ei;
    const int* dst = ei + E;
    float* out = (float*)d_out;

    k_zero_prep<<<2048, 256>>>(W2, root2, N);
    k_edge1<<<(E + 255) / 256, 256>>>(x, ea, src, dst, E);
    k_h1<<<(N * 16 + 255) / 256, 256>>>(x, W1, root1, b1, N);
    k_edge2<<<(E * 16 + 255) / 256, 256>>>(E);
    k_gemm_mma<<<(N + 127) / 128, 256>>>(b2, batch, N);
    k_mlp<<<NG, 128>>>(Wf1, bf1, Wf2, bf2, batch, N, out);
}

// round 13
// speedup vs baseline: 1.0711x; 1.0483x over previous
#include <cuda_runtime.h>
#include <cuda_bf16.h>
#include <cstdint>

#define KS   5
#define K2   25
#define C1   32
#define C2   64
#define NG   64
#define NMAX 20000
#define EMAX 320000
#define KTOT 800
#define ZB   1024   // zero blocks fused into edge1 grid

// ---------------- scratch (device globals; no allocations) ----------------
__device__ float        g_T[NMAX * K2];
__device__ float        g_deg[NMAX];
__device__ float        g_dinv[NMAX];
__device__ unsigned int g_h1b[NMAX * 16];     // h1 bf16x2 packed [N][16]
__device__ unsigned int g_Sb[NMAX * 400];     // S accum bf16x2 [N][25][16] (32MB)
__device__ uint2        g_W2f[56 * 8 * 32];   // B fragments (+root2 at 52-53)
__device__ float        g_pool[NG * C2];
__device__ uint4        g_rec[EMAX];          // {src|wi0<<20, dst, bw01 bf16x2, bw23 bf16x2}

// ---------------- helpers ----------------
__device__ __forceinline__ uint32_t smem_u32(const void* p) {
    uint32_t a;
    asm("{ .reg .u64 t; cvta.to.shared.u64 t, %1; cvt.u32.u64 %0, t; }" : "=r"(a) : "l"(p));
    return a;
}
__device__ __forceinline__ void red_bf162(unsigned int* addr, unsigned int v) {
    asm volatile("red.global.add.noftz.bf16x2 [%0], %1;" :: "l"(addr), "r"(v) : "memory");
}
__device__ __forceinline__ void red_f32(float* addr, float v) {
    asm volatile("red.global.add.f32 [%0], %1;" :: "l"(addr), "f"(v) : "memory");
}
__device__ __forceinline__ void ldmatrix_x4(uint32_t& a0, uint32_t& a1, uint32_t& a2,
                                            uint32_t& a3, uint32_t addr) {
    asm volatile("ldmatrix.sync.aligned.m8n8.x4.shared.b16 {%0,%1,%2,%3}, [%4];"
                 : "=r"(a0), "=r"(a1), "=r"(a2), "=r"(a3) : "r"(addr));
}
__device__ __forceinline__ void mma_bf16(float* c, uint32_t a0, uint32_t a1, uint32_t a2,
                                         uint32_t a3, uint32_t b0, uint32_t b1) {
    asm volatile(
        "mma.sync.aligned.m16n8k16.row.col.f32.bf16.bf16.f32 "
        "{%0,%1,%2,%3}, {%4,%5,%6,%7}, {%8,%9}, {%0,%1,%2,%3};"
        : "+f"(c[0]), "+f"(c[1]), "+f"(c[2]), "+f"(c[3])
        : "r"(a0), "r"(a1), "r"(a2), "r"(a3), "r"(b0), "r"(b1));
}

// ---------------- basis (wi0 form: indices are wi0, +1, +5, +6) ----------------
__device__ __forceinline__ void basis2w(float a0, float a1, int& wi0, float* bw) {
    float v0 = a0 * (KS - 1), v1 = a1 * (KS - 1);
    int k0 = (int)floorf(v0); k0 = min(max(k0, 0), KS - 2);
    int k1 = (int)floorf(v1); k1 = min(max(k1, 0), KS - 2);
    float f0 = v0 - (float)k0, f1 = v1 - (float)k1;
    float g0 = 1.f - f0, g1 = 1.f - f1;
    wi0 = k0 + KS * k1;
    bw[0] = g0 * g1;
    bw[1] = f0 * g1;
    bw[2] = g0 * f1;
    bw[3] = f0 * f1;
}

// ---------------- small pre-pass: zero T/deg/pool + prep B fragments ----------------
__global__ void k_pre(const float* __restrict__ W2, const float* __restrict__ root2, int N) {
    int tid = blockIdx.x * blockDim.x + threadIdx.x;
    int stride = gridDim.x * blockDim.x;
    int nT = N * K2;
    for (int i = tid; i < nT; i += stride) g_T[i] = 0.f;
    for (int i = tid; i < N; i += stride) g_deg[i] = 0.f;
    for (int i = tid; i < NG * C2; i += stride) g_pool[i] = 0.f;
    if (tid < 56 * 8 * 32) {
        int t = tid;
        int lane = t & 31, ng = (t >> 5) & 7, sg = t >> 8;
        int gid = lane >> 2, tig = lane & 3;
        int n = ng * 8 + gid;
        int k = sg * 16 + tig * 2;
        float f0 = 0.f, f1 = 0.f, f2 = 0.f, f3 = 0.f;
        if (sg < 50) {
            f0 = W2[k * C2 + n];       f1 = W2[(k + 1) * C2 + n];
            f2 = W2[(k + 8) * C2 + n]; f3 = W2[(k + 9) * C2 + n];
        } else if (sg >= 52 && sg < 54) {
            int kr = k - 832;
            f0 = root2[kr * C2 + n];       f1 = root2[(kr + 1) * C2 + n];
            f2 = root2[(kr + 8) * C2 + n]; f3 = root2[(kr + 9) * C2 + n];
        }
        __nv_bfloat162 lo = __float22bfloat162_rn(make_float2(f0, f1));
        __nv_bfloat162 hi = __float22bfloat162_rn(make_float2(f2, f3));
        g_W2f[t] = make_uint2(*(uint32_t*)&lo, *(uint32_t*)&hi);
    }
}

// ---------------- edge pass 1 + fused S-zero (leading ZB blocks memset S) ----------------
__global__ void k_edge1(const float* __restrict__ x, const float* __restrict__ ea,
                        const int* __restrict__ src, const int* __restrict__ dst,
                        int E, int N) {
    if (blockIdx.x < ZB) {
        // zero a 32KB slice of S (spread across the grid-start; DRAM-bound, rides
        // alongside the latency-bound edge work)
        long total4 = (long)N * 100;                   // uint4 count
        long per = (total4 + ZB - 1) / ZB;
        long base = (long)blockIdx.x * per;
        long end = min(base + per, total4);
        uint4* S4 = (uint4*)g_Sb;
        uint4 z4 = make_uint4(0u, 0u, 0u, 0u);
        for (long i = base + threadIdx.x; i < end; i += blockDim.x) S4[i] = z4;
        return;
    }
    int e = (blockIdx.x - ZB) * blockDim.x + threadIdx.x;
    if (e >= E) return;
    int wi0; float bw[4];
    float2 eav = ((const float2*)ea)[e];
    basis2w(eav.x, eav.y, wi0, bw);
    int s = src[e];
    float xs = x[s];
    int d = dst[e];
    float* Tp = g_T + d * K2 + wi0;
    atomicAdd(Tp,     bw[0] * xs);
    atomicAdd(Tp + 1, bw[1] * xs);
    atomicAdd(Tp + 5, bw[2] * xs);
    atomicAdd(Tp + 6, bw[3] * xs);
    atomicAdd(g_deg + d, 1.f);
    __nv_bfloat162 c01 = __float22bfloat162_rn(make_float2(bw[0], bw[1]));
    __nv_bfloat162 c23 = __float22bfloat162_rn(make_float2(bw[2], bw[3]));
    g_rec[e] = make_uint4((uint32_t)s | ((uint32_t)wi0 << 20), (uint32_t)d,
                          *(uint32_t*)&c01, *(uint32_t*)&c23);
}

// ---------------- layer-1 node update (per-thread form, atomic-free) ----------------
__global__ void k_h1(const float* __restrict__ x, const float* __restrict__ W1,
                     const float* __restrict__ root1, const float* __restrict__ b1, int N) {
    int t = blockIdx.x * blockDim.x + threadIdx.x;
    if (t >= N * 16) return;
    int n = t >> 4, c2 = t & 15;
    const float* Tp = g_T + n * K2;
    float a0 = 0.f, a1 = 0.f;
#pragma unroll
    for (int w = 0; w < K2; w++) {
        float tv = Tp[w];
        a0 += tv * W1[w * C1 + 2 * c2];
        a1 += tv * W1[w * C1 + 2 * c2 + 1];
    }
    float dinv = 1.f / fmaxf(g_deg[n], 1.f);
    float xn = x[n];
    float h0 = fmaxf(a0 * dinv + xn * root1[2 * c2]     + b1[2 * c2],     0.f);
    float h1 = fmaxf(a1 * dinv + xn * root1[2 * c2 + 1] + b1[2 * c2 + 1], 0.f);
    __nv_bfloat162 hb = __float22bfloat162_rn(make_float2(h0, h1));
    g_h1b[t] = *(unsigned int*)&hb;
    if (c2 == 0) g_dinv[n] = dinv;
}

// ---------------- edge pass 2: 16 lanes/edge, 16B record + dinv + h1 gather ----------------
__global__ void k_edge2(int E) {
    int gt = blockIdx.x * blockDim.x + threadIdx.x;
    int lane = gt & 31;
    int warp = gt >> 5;
    int e = warp * 2 + (lane >> 4);
    int hl = lane & 15;
    if (e >= E) return;
    uint4 r = g_rec[e];
    int s   = (int)(r.x & 0xFFFFFu);
    int wi0 = (int)(r.x >> 20);
    int d   = (int)r.y;
    float2 bw01 = __bfloat1622float2(*(__nv_bfloat162*)&r.z);
    float2 bw23 = __bfloat1622float2(*(__nv_bfloat162*)&r.w);
    float dinv = g_dinv[d];
    float2 h = __bfloat1622float2(*(__nv_bfloat162*)&g_h1b[s * 16 + hl]);
    h.x *= dinv; h.y *= dinv;
    unsigned int* base = g_Sb + d * 400 + wi0 * 16 + hl;
    {
        __nv_bfloat162 v = __float22bfloat162_rn(make_float2(bw01.x * h.x, bw01.x * h.y));
        red_bf162(base, *(unsigned int*)&v);
    }
    {
        __nv_bfloat162 v = __float22bfloat162_rn(make_float2(bw01.y * h.x, bw01.y * h.y));
        red_bf162(base + 16, *(unsigned int*)&v);
    }
    {
        __nv_bfloat162 v = __float22bfloat162_rn(make_float2(bw23.x * h.x, bw23.x * h.y));
        red_bf162(base + 80, *(unsigned int*)&v);
    }
    {
        __nv_bfloat162 v = __float22bfloat162_rn(make_float2(bw23.y * h.x, bw23.y * h.y));
        red_bf162(base + 96, *(unsigned int*)&v);
    }
}

// ---------------- fused GEMM (HMMA) + layer-2 epilogue + pooling ----------------
__global__ void __launch_bounds__(256) k_gemm_mma(const float* __restrict__ b2,
                                                  const int* __restrict__ batch, int N) {
    __shared__ __align__(16) uint8_t smA[16384];
    int tid = threadIdx.x;
    int warp = tid >> 5, lane = tid & 31;
    int gid = lane >> 2, tig = lane & 3;
    int rowBase = blockIdx.x * 128;
    uint32_t smA_b = smem_u32(smA);

    int rowA[4], chA[4], stoff[4];
    bool inb[4];
#pragma unroll
    for (int j = 0; j < 4; j++) {
        int c = tid + 256 * j;
        rowA[j] = c >> 3; chA[j] = c & 7;
        stoff[j] = rowA[j] * 128 + ((chA[j] ^ (rowA[j] & 7)) << 4);
        inb[j] = (rowBase + rowA[j]) < N;
    }

    float acc[8][4];
#pragma unroll
    for (int g = 0; g < 8; g++)
#pragma unroll
        for (int j = 0; j < 4; j++) acc[g][j] = 0.f;

    uint4 v[4];
#pragma unroll
    for (int j = 0; j < 4; j++) {
        v[j] = make_uint4(0u, 0u, 0u, 0u);
        if (inb[j])
            v[j] = *(const uint4*)(g_Sb + (rowBase + rowA[j]) * 400 + chA[j] * 4);
    }

    for (int c0 = 0; c0 < 14; c0++) {
#pragma unroll
        for (int j = 0; j < 4; j++) *(uint4*)(smA + stoff[j]) = v[j];
        __syncthreads();
        if (c0 < 13) {
            int cn = c0 + 1;
#pragma unroll
            for (int j = 0; j < 4; j++) {
                v[j] = make_uint4(0u, 0u, 0u, 0u);
                if (inb[j]) {
                    if (cn < 13) {
                        int off = cn * 32 + chA[j] * 4;
                        if (off < 400)
                            v[j] = *(const uint4*)(g_Sb + (rowBase + rowA[j]) * 400 + off);
                    } else if (chA[j] < 4) {
                        v[j] = *(const uint4*)(g_h1b + (rowBase + rowA[j]) * 16 + chA[j] * 4);
                    }
                }
            }
        }
#pragma unroll
        for (int ks = 0; ks < 4; ks++) {
            int mrow = warp * 16 + (lane & 15);
            uint32_t addr = smA_b + mrow * 128 + (((ks * 2 + (lane >> 4)) ^ (mrow & 7)) << 4);
            uint32_t a0, a1, a2, a3;
            ldmatrix_x4(a0, a1, a2, a3, addr);
            int sg = c0 * 4 + ks;
            const uint2* bf = g_W2f + (sg << 8) + lane;
#pragma unroll
            for (int ng = 0; ng < 8; ng++) {
                uint2 b = bf[ng << 5];
                mma_bf16(acc[ng], a0, a1, a2, a3, b.x, b.y);
            }
        }
        __syncthreads();
    }

    int r0 = rowBase + warp * 16 + gid;
    int r1 = r0 + 8;
    int bt0 = (r0 < N) ? batch[r0] : -1;
    int bt1 = (r1 < N) ? batch[r1] : -1;
#pragma unroll
    for (int ng = 0; ng < 8; ng++) {
        int col = ng * 8 + tig * 2;
        float2 bb = *(const float2*)(b2 + col);
        if (bt0 >= 0) {
            red_f32(g_pool + bt0 * C2 + col,     fmaxf(acc[ng][0] + bb.x, 0.f));
            red_f32(g_pool + bt0 * C2 + col + 1, fmaxf(acc[ng][1] + bb.y, 0.f));
        }
        if (bt1 >= 0) {
            red_f32(g_pool + bt1 * C2 + col,     fmaxf(acc[ng][2] + bb.x, 0.f));
            red_f32(g_pool + bt1 * C2 + col + 1, fmaxf(acc[ng][3] + bb.y, 0.f));
        }
    }
}

// ---------------- head MLP + log_softmax (cnt via binary search on sorted batch) ----------------
__global__ void k_mlp(const float* __restrict__ Wf1, const float* __restrict__ bf1,
                      const float* __restrict__ Wf2, const float* __restrict__ bf2,
                      const int* __restrict__ batch, int N,
                      float* __restrict__ out) {
    int b = blockIdx.x;
    int j = threadIdx.x;
    __shared__ float gs[C2];
    __shared__ float ts[128];
    __shared__ float lg[10];
    __shared__ float s_cinv;
    if (j == 0) {
        int lo = 0, hi = N;
        while (lo < hi) { int m = (lo + hi) >> 1; if (batch[m] < b) lo = m + 1; else hi = m; }
        int lo2 = lo; hi = N;
        while (lo2 < hi) { int m = (lo2 + hi) >> 1; if (batch[m] < b + 1) lo2 = m + 1; else hi = m; }
        s_cinv = 1.f / fmaxf((float)(lo2 - lo), 1.f);
    }
    __syncthreads();
    if (j < C2) gs[j] = g_pool[b * C2 + j] * s_cinv;
    __syncthreads();
    float t = bf1[j];
#pragma unroll
    for (int k = 0; k < C2; k++) t += gs[k] * Wf1[k * 128 + j];
    ts[j] = fmaxf(t, 0.f);
    __syncthreads();
    if (j < 10) {
        float a = bf2[j];
#pragma unroll
        for (int q = 0; q < 128; q++) a += ts[q] * Wf2[q * 10 + j];
        lg[j] = a;
    }
    __syncthreads();
    if (j == 0) {
        float m = lg[0];
#pragma unroll
        for (int q = 1; q < 10; q++) m = fmaxf(m, lg[q]);
        float s = 0.f;
#pragma unroll
        for (int q = 0; q < 10; q++) s += expf(lg[q] - m);
        float l = logf(s) + m;
#pragma unroll
        for (int q = 0; q < 10; q++) out[b * 10 + q] = lg[q] - l;
    }
}

// ---------------- launch ----------------
extern "C" void kernel_launch(void* const* d_in, const int* in_sizes, int n_in,
                              void* d_out, int out_size) {
    const float* x     = (const float*)d_in[0];
    const float* ea    = (const float*)d_in[1];
    const float* W1    = (const float*)d_in[2];
    const float* root1 = (const float*)d_in[3];
    const float* b1    = (const float*)d_in[4];
    const float* W2    = (const float*)d_in[5];
    const float* root2 = (const float*)d_in[6];
    const float* b2    = (const float*)d_in[7];
    const float* Wf1   = (const float*)d_in[8];
    const float* bf1   = (const float*)d_in[9];
    const float* Wf2   = (const float*)d_in[10];
    const float* bf2   = (const float*)d_in[11];
    const int*   ei    = (const int*)d_in[12];
    const int*   batch = (const int*)d_in[13];

    int N = in_sizes[0];
    int E = in_sizes[1] / 2;
    const int* src = ei;
    const int* dst = ei + E;
    float* out = (float*)d_out;

    k_pre<<<264, 256>>>(W2, root2, N);
    k_edge1<<<ZB + (E + 255) / 256, 256>>>(x, ea, src, dst, E, N);
    k_h1<<<(N * 16 + 255) / 256, 256>>>(x, W1, root1, b1, N);
    k_edge2<<<(E * 16 + 255) / 256, 256>>>(E);
    k_gemm_mma<<<(N + 127) / 128, 256>>>(b2, batch, N);
    k_mlp<<<NG, 128>>>(Wf1, bf1, Wf2, bf2, batch, N, out);
}

// round 14
// speedup vs baseline: 1.0803x; 1.0086x over previous
#include <cuda_runtime.h>
#include <cuda_bf16.h>
#include <cstdint>

#define KS   5
#define K2   25
#define C1   32
#define C2   64
#define NG   64
#define NMAX 20000
#define EMAX 320000
#define KTOT 800
#define ZB   1024   // zero blocks fused into edge1 grid

// ---------------- scratch (device globals; no allocations) ----------------
__device__ float        g_T[NMAX * K2];
__device__ float        g_deg[NMAX];
__device__ float        g_dinv[NMAX];
__device__ unsigned int g_h1b[NMAX * 16];     // h1 bf16x2 packed [N][16]
__device__ unsigned int g_Sb[NMAX * 400];     // S accum bf16x2 [N][25][16] (32MB), UNSCALED messages
__device__ uint2        g_W2f[56 * 8 * 32];   // B fragments (+root2 at 52-53)
__device__ float        g_pool[NG * C2];
__device__ uint4        g_rec[EMAX];          // {src|wi0<<20, dst, bw01 bf16x2, bw23 bf16x2}

// ---------------- helpers ----------------
__device__ __forceinline__ uint32_t smem_u32(const void* p) {
    uint32_t a;
    asm("{ .reg .u64 t; cvta.to.shared.u64 t, %1; cvt.u32.u64 %0, t; }" : "=r"(a) : "l"(p));
    return a;
}
__device__ __forceinline__ void red_bf162(unsigned int* addr, unsigned int v) {
    asm volatile("red.global.add.noftz.bf16x2 [%0], %1;" :: "l"(addr), "r"(v) : "memory");
}
__device__ __forceinline__ void red_f32(float* addr, float v) {
    asm volatile("red.global.add.f32 [%0], %1;" :: "l"(addr), "f"(v) : "memory");
}
__device__ __forceinline__ void ldmatrix_x4(uint32_t& a0, uint32_t& a1, uint32_t& a2,
                                            uint32_t& a3, uint32_t addr) {
    asm volatile("ldmatrix.sync.aligned.m8n8.x4.shared.b16 {%0,%1,%2,%3}, [%4];"
                 : "=r"(a0), "=r"(a1), "=r"(a2), "=r"(a3) : "r"(addr));
}
__device__ __forceinline__ void mma_bf16(float* c, uint32_t a0, uint32_t a1, uint32_t a2,
                                         uint32_t a3, uint32_t b0, uint32_t b1) {
    asm volatile(
        "mma.sync.aligned.m16n8k16.row.col.f32.bf16.bf16.f32 "
        "{%0,%1,%2,%3}, {%4,%5,%6,%7}, {%8,%9}, {%0,%1,%2,%3};"
        : "+f"(c[0]), "+f"(c[1]), "+f"(c[2]), "+f"(c[3])
        : "r"(a0), "r"(a1), "r"(a2), "r"(a3), "r"(b0), "r"(b1));
}

// ---------------- basis (wi0 form: indices are wi0, +1, +5, +6) ----------------
__device__ __forceinline__ void basis2w(float a0, float a1, int& wi0, float* bw) {
    float v0 = a0 * (KS - 1), v1 = a1 * (KS - 1);
    int k0 = (int)floorf(v0); k0 = min(max(k0, 0), KS - 2);
    int k1 = (int)floorf(v1); k1 = min(max(k1, 0), KS - 2);
    float f0 = v0 - (float)k0, f1 = v1 - (float)k1;
    float g0 = 1.f - f0, g1 = 1.f - f1;
    wi0 = k0 + KS * k1;
    bw[0] = g0 * g1;
    bw[1] = f0 * g1;
    bw[2] = g0 * f1;
    bw[3] = f0 * f1;
}

// ---------------- small pre-pass: zero T/deg/pool + prep B fragments ----------------
__global__ void k_pre(const float* __restrict__ W2, const float* __restrict__ root2, int N) {
    int tid = blockIdx.x * blockDim.x + threadIdx.x;
    int stride = gridDim.x * blockDim.x;
    int nT = N * K2;
    for (int i = tid; i < nT; i += stride) g_T[i] = 0.f;
    for (int i = tid; i < N; i += stride) g_deg[i] = 0.f;
    for (int i = tid; i < NG * C2; i += stride) g_pool[i] = 0.f;
    if (tid < 56 * 8 * 32) {
        int t = tid;
        int lane = t & 31, ng = (t >> 5) & 7, sg = t >> 8;
        int gid = lane >> 2, tig = lane & 3;
        int n = ng * 8 + gid;
        int k = sg * 16 + tig * 2;
        float f0 = 0.f, f1 = 0.f, f2 = 0.f, f3 = 0.f;
        if (sg < 50) {
            f0 = W2[k * C2 + n];       f1 = W2[(k + 1) * C2 + n];
            f2 = W2[(k + 8) * C2 + n]; f3 = W2[(k + 9) * C2 + n];
        } else if (sg >= 52 && sg < 54) {
            int kr = k - 832;
            f0 = root2[kr * C2 + n];       f1 = root2[(kr + 1) * C2 + n];
            f2 = root2[(kr + 8) * C2 + n]; f3 = root2[(kr + 9) * C2 + n];
        }
        __nv_bfloat162 lo = __float22bfloat162_rn(make_float2(f0, f1));
        __nv_bfloat162 hi = __float22bfloat162_rn(make_float2(f2, f3));
        g_W2f[t] = make_uint2(*(uint32_t*)&lo, *(uint32_t*)&hi);
    }
}

// ---------------- edge pass 1 + fused S-zero (leading ZB blocks memset S) ----------------
__global__ void k_edge1(const float* __restrict__ x, const float* __restrict__ ea,
                        const int* __restrict__ src, const int* __restrict__ dst,
                        int E, int N) {
    if (blockIdx.x < ZB) {
        long total4 = (long)N * 100;                   // uint4 count
        long per = (total4 + ZB - 1) / ZB;
        long base = (long)blockIdx.x * per;
        long end = min(base + per, total4);
        uint4* S4 = (uint4*)g_Sb;
        uint4 z4 = make_uint4(0u, 0u, 0u, 0u);
        for (long i = base + threadIdx.x; i < end; i += blockDim.x) S4[i] = z4;
        return;
    }
    int e = (blockIdx.x - ZB) * blockDim.x + threadIdx.x;
    if (e >= E) return;
    int wi0; float bw[4];
    float2 eav = ((const float2*)ea)[e];
    basis2w(eav.x, eav.y, wi0, bw);
    int s = src[e];
    float xs = x[s];
    int d = dst[e];
    float* Tp = g_T + d * K2 + wi0;
    atomicAdd(Tp,     bw[0] * xs);
    atomicAdd(Tp + 1, bw[1] * xs);
    atomicAdd(Tp + 5, bw[2] * xs);
    atomicAdd(Tp + 6, bw[3] * xs);
    atomicAdd(g_deg + d, 1.f);
    __nv_bfloat162 c01 = __float22bfloat162_rn(make_float2(bw[0], bw[1]));
    __nv_bfloat162 c23 = __float22bfloat162_rn(make_float2(bw[2], bw[3]));
    g_rec[e] = make_uint4((uint32_t)s | ((uint32_t)wi0 << 20), (uint32_t)d,
                          *(uint32_t*)&c01, *(uint32_t*)&c23);
}

// ---------------- layer-1 node update (per-thread form, atomic-free) ----------------
__global__ void k_h1(const float* __restrict__ x, const float* __restrict__ W1,
                     const float* __restrict__ root1, const float* __restrict__ b1, int N) {
    int t = blockIdx.x * blockDim.x + threadIdx.x;
    if (t >= N * 16) return;
    int n = t >> 4, c2 = t & 15;
    const float* Tp = g_T + n * K2;
    float a0 = 0.f, a1 = 0.f;
#pragma unroll
    for (int w = 0; w < K2; w++) {
        float tv = Tp[w];
        a0 += tv * W1[w * C1 + 2 * c2];
        a1 += tv * W1[w * C1 + 2 * c2 + 1];
    }
    float dinv = 1.f / fmaxf(g_deg[n], 1.f);
    float xn = x[n];
    float h0 = fmaxf(a0 * dinv + xn * root1[2 * c2]     + b1[2 * c2],     0.f);
    float h1 = fmaxf(a1 * dinv + xn * root1[2 * c2 + 1] + b1[2 * c2 + 1], 0.f);
    __nv_bfloat162 hb = __float22bfloat162_rn(make_float2(h0, h1));
    g_h1b[t] = *(unsigned int*)&hb;
    if (c2 == 0) g_dinv[n] = dinv;
}

// ---------------- edge pass 2: 16 lanes/edge, 16B record + h1 gather (no dinv) ----------------
__global__ void k_edge2(int E) {
    int gt = blockIdx.x * blockDim.x + threadIdx.x;
    int lane = gt & 31;
    int warp = gt >> 5;
    int e = warp * 2 + (lane >> 4);
    int hl = lane & 15;
    if (e >= E) return;
    uint4 r = g_rec[e];
    int s   = (int)(r.x & 0xFFFFFu);
    int wi0 = (int)(r.x >> 20);
    int d   = (int)r.y;
    float2 bw01 = __bfloat1622float2(*(__nv_bfloat162*)&r.z);
    float2 bw23 = __bfloat1622float2(*(__nv_bfloat162*)&r.w);
    float2 h = __bfloat1622float2(*(__nv_bfloat162*)&g_h1b[s * 16 + hl]);
    unsigned int* base = g_Sb + d * 400 + wi0 * 16 + hl;
    {
        __nv_bfloat162 v = __float22bfloat162_rn(make_float2(bw01.x * h.x, bw01.x * h.y));
        red_bf162(base, *(unsigned int*)&v);
    }
    {
        __nv_bfloat162 v = __float22bfloat162_rn(make_float2(bw01.y * h.x, bw01.y * h.y));
        red_bf162(base + 16, *(unsigned int*)&v);
    }
    {
        __nv_bfloat162 v = __float22bfloat162_rn(make_float2(bw23.x * h.x, bw23.x * h.y));
        red_bf162(base + 80, *(unsigned int*)&v);
    }
    {
        __nv_bfloat162 v = __float22bfloat162_rn(make_float2(bw23.y * h.x, bw23.y * h.y));
        red_bf162(base + 96, *(unsigned int*)&v);
    }
}

// ---------------- fused GEMM (HMMA) + per-row dinv scale + layer-2 epilogue + pooling ----------------
__global__ void __launch_bounds__(256) k_gemm_mma(const float* __restrict__ b2,
                                                  const int* __restrict__ batch, int N) {
    __shared__ __align__(16) uint8_t smA[16384];
    int tid = threadIdx.x;
    int warp = tid >> 5, lane = tid & 31;
    int gid = lane >> 2, tig = lane & 3;
    int rowBase = blockIdx.x * 128;
    uint32_t smA_b = smem_u32(smA);

    int rowA[4], chA[4], stoff[4];
    bool inb[4];
#pragma unroll
    for (int j = 0; j < 4; j++) {
        int c = tid + 256 * j;
        rowA[j] = c >> 3; chA[j] = c & 7;
        stoff[j] = rowA[j] * 128 + ((chA[j] ^ (rowA[j] & 7)) << 4);
        inb[j] = (rowBase + rowA[j]) < N;
    }

    float acc[8][4];
#pragma unroll
    for (int g = 0; g < 8; g++)
#pragma unroll
        for (int j = 0; j < 4; j++) acc[g][j] = 0.f;

    int r0 = rowBase + warp * 16 + gid;
    int r1 = r0 + 8;

    uint4 v[4];
#pragma unroll
    for (int j = 0; j < 4; j++) {
        v[j] = make_uint4(0u, 0u, 0u, 0u);
        if (inb[j])
            v[j] = *(const uint4*)(g_Sb + (rowBase + rowA[j]) * 400 + chA[j] * 4);
    }

    for (int c0 = 0; c0 < 14; c0++) {
#pragma unroll
        for (int j = 0; j < 4; j++) *(uint4*)(smA + stoff[j]) = v[j];
        __syncthreads();
        if (c0 < 13) {
            int cn = c0 + 1;
#pragma unroll
            for (int j = 0; j < 4; j++) {
                v[j] = make_uint4(0u, 0u, 0u, 0u);
                if (inb[j]) {
                    if (cn < 13) {
                        int off = cn * 32 + chA[j] * 4;
                        if (off < 400)
                            v[j] = *(const uint4*)(g_Sb + (rowBase + rowA[j]) * 400 + off);
                    } else if (chA[j] < 4) {
                        v[j] = *(const uint4*)(g_h1b + (rowBase + rowA[j]) * 16 + chA[j] * 4);
                    }
                }
            }
        }
#pragma unroll
        for (int ks = 0; ks < 4; ks++) {
            int mrow = warp * 16 + (lane & 15);
            uint32_t addr = smA_b + mrow * 128 + (((ks * 2 + (lane >> 4)) ^ (mrow & 7)) << 4);
            uint32_t a0, a1, a2, a3;
            ldmatrix_x4(a0, a1, a2, a3, addr);
            int sg = c0 * 4 + ks;
            const uint2* bf = g_W2f + (sg << 8) + lane;
#pragma unroll
            for (int ng = 0; ng < 8; ng++) {
                uint2 b = bf[ng << 5];
                mma_bf16(acc[ng], a0, a1, a2, a3, b.x, b.y);
            }
        }
        // after the last S chunk (before the root2 chunk), scale S-part by dinv[row]
        if (c0 == 12) {
            float di0 = (r0 < N) ? g_dinv[r0] : 0.f;
            float di1 = (r1 < N) ? g_dinv[r1] : 0.f;
#pragma unroll
            for (int ng = 0; ng < 8; ng++) {
                acc[ng][0] *= di0; acc[ng][1] *= di0;
                acc[ng][2] *= di1; acc[ng][3] *= di1;
            }
        }
        __syncthreads();
    }

    int bt0 = (r0 < N) ? batch[r0] : -1;
    int bt1 = (r1 < N) ? batch[r1] : -1;
#pragma unroll
    for (int ng = 0; ng < 8; ng++) {
        int col = ng * 8 + tig * 2;
        float2 bb = *(const float2*)(b2 + col);
        if (bt0 >= 0) {
            red_f32(g_pool + bt0 * C2 + col,     fmaxf(acc[ng][0] + bb.x, 0.f));
            red_f32(g_pool + bt0 * C2 + col + 1, fmaxf(acc[ng][1] + bb.y, 0.f));
        }
        if (bt1 >= 0) {
            red_f32(g_pool + bt1 * C2 + col,     fmaxf(acc[ng][2] + bb.x, 0.f));
            red_f32(g_pool + bt1 * C2 + col + 1, fmaxf(acc[ng][3] + bb.y, 0.f));
        }
    }
}

// ---------------- head MLP + log_softmax (cnt via binary search on sorted batch) ----------------
__global__ void k_mlp(const float* __restrict__ Wf1, const float* __restrict__ bf1,
                      const float* __restrict__ Wf2, const float* __restrict__ bf2,
                      const int* __restrict__ batch, int N,
                      float* __restrict__ out) {
    int b = blockIdx.x;
    int j = threadIdx.x;
    __shared__ float gs[C2];
    __shared__ float ts[128];
    __shared__ float lg[10];
    __shared__ float s_cinv;
    if (j == 0) {
        int lo = 0, hi = N;
        while (lo < hi) { int m = (lo + hi) >> 1; if (batch[m] < b) lo = m + 1; else hi = m; }
        int lo2 = lo; hi = N;
        while (lo2 < hi) { int m = (lo2 + hi) >> 1; if (batch[m] < b + 1) lo2 = m + 1; else hi = m; }
        s_cinv = 1.f / fmaxf((float)(lo2 - lo), 1.f);
    }
    __syncthreads();
    if (j < C2) gs[j] = g_pool[b * C2 + j] * s_cinv;
    __syncthreads();
    float t = bf1[j];
#pragma unroll
    for (int k = 0; k < C2; k++) t += gs[k] * Wf1[k * 128 + j];
    ts[j] = fmaxf(t, 0.f);
    __syncthreads();
    if (j < 10) {
        float a = bf2[j];
#pragma unroll
        for (int q = 0; q < 128; q++) a += ts[q] * Wf2[q * 10 + j];
        lg[j] = a;
    }
    __syncthreads();
    if (j == 0) {
        float m = lg[0];
#pragma unroll
        for (int q = 1; q < 10; q++) m = fmaxf(m, lg[q]);
        float s = 0.f;
#pragma unroll
        for (int q = 0; q < 10; q++) s += expf(lg[q] - m);
        float l = logf(s) + m;
#pragma unroll
        for (int q = 0; q < 10; q++) out[b * 10 + q] = lg[q] - l;
    }
}

// ---------------- launch ----------------
extern "C" void kernel_launch(void* const* d_in, const int* in_sizes, int n_in,
                              void* d_out, int out_size) {
    const float* x     = (const float*)d_in[0];
    const float* ea    = (const float*)d_in[1];
    const float* W1    = (const float*)d_in[2];
    const float* root1 = (const float*)d_in[3];
    const float* b1    = (const float*)d_in[4];
    const float* W2    = (const float*)d_in[5];
    const float* root2 = (const float*)d_in[6];
    const float* b2    = (const float*)d_in[7];
    const float* Wf1   = (const float*)d_in[8];
    const float* bf1   = (const float*)d_in[9];
    const float* Wf2   = (const float*)d_in[10];
    const float* bf2   = (const float*)d_in[11];
    const int*   ei    = (const int*)d_in[12];
    const int*   batch = (const int*)d_in[13];

    int N = in_sizes[0];
    int E = in_sizes[1] / 2;
    const int* src = ei;
    const int* dst = ei + E;
    float* out = (float*)d_out;

    k_pre<<<264, 256>>>(W2, root2, N);
    k_edge1<<<ZB + (E + 255) / 256, 256>>>(x, ea, src, dst, E, N);
    k_h1<<<(N * 16 + 255) / 256, 256>>>(x, W1, root1, b1, N);
    k_edge2<<<(E * 16 + 255) / 256, 256>>>(E);
    k_gemm_mma<<<(N + 127) / 128, 256>>>(b2, batch, N);
    k_mlp<<<NG, 128>>>(Wf1, bf1, Wf2, bf2, batch, N, out);
}

// round 15
// speedup vs baseline: 1.1232x; 1.0397x over previous
#include <cuda_runtime.h>
#include <cuda_bf16.h>
#include <cstdint>

#define KS   5
#define K2   25
#define C1   32
#define C2   64
#define NG   64
#define NMAX 20000
#define EMAX 320000
#define KTOT 800
#define ZB   1024   // zero/prep blocks fused into edge1 grid

// ---------------- scratch (device globals; .bss-zeroed at load) ----------------
__device__ float        g_T[NMAX * K2];       // zeroed at tail of k_gemm_mma each call
__device__ float        g_deg[NMAX];          // idem
__device__ float        g_dinv[NMAX];
__device__ unsigned int g_h1b[NMAX * 16];     // h1 bf16x2 packed [N][16]
__device__ unsigned int g_Sb[NMAX * 400];     // S accum (32MB); zeroed by edge1's ZB blocks
__device__ uint2        g_W2f[56 * 8 * 32];   // B fragments; built by edge1's first 56 blocks
__device__ float        g_pool[NG * C2];      // zeroed at tail of k_mlp each call
__device__ uint4        g_rec[EMAX];          // {src|wi0<<20, dst, bw01 bf16x2, bw23 bf16x2}

// ---------------- helpers ----------------
__device__ __forceinline__ uint32_t smem_u32(const void* p) {
    uint32_t a;
    asm("{ .reg .u64 t; cvta.to.shared.u64 t, %1; cvt.u32.u64 %0, t; }" : "=r"(a) : "l"(p));
    return a;
}
__device__ __forceinline__ void red_bf162(unsigned int* addr, unsigned int v) {
    asm volatile("red.global.add.noftz.bf16x2 [%0], %1;" :: "l"(addr), "r"(v) : "memory");
}
__device__ __forceinline__ void red_f32(float* addr, float v) {
    asm volatile("red.global.add.f32 [%0], %1;" :: "l"(addr), "f"(v) : "memory");
}
__device__ __forceinline__ void ldmatrix_x4(uint32_t& a0, uint32_t& a1, uint32_t& a2,
                                            uint32_t& a3, uint32_t addr) {
    asm volatile("ldmatrix.sync.aligned.m8n8.x4.shared.b16 {%0,%1,%2,%3}, [%4];"
                 : "=r"(a0), "=r"(a1), "=r"(a2), "=r"(a3) : "r"(addr));
}
__device__ __forceinline__ void mma_bf16(float* c, uint32_t a0, uint32_t a1, uint32_t a2,
                                         uint32_t a3, uint32_t b0, uint32_t b1) {
    asm volatile(
        "mma.sync.aligned.m16n8k16.row.col.f32.bf16.bf16.f32 "
        "{%0,%1,%2,%3}, {%4,%5,%6,%7}, {%8,%9}, {%0,%1,%2,%3};"
        : "+f"(c[0]), "+f"(c[1]), "+f"(c[2]), "+f"(c[3])
        : "r"(a0), "r"(a1), "r"(a2), "r"(a3), "r"(b0), "r"(b1));
}

// ---------------- basis (wi0 form: indices are wi0, +1, +5, +6) ----------------
__device__ __forceinline__ void basis2w(float a0, float a1, int& wi0, float* bw) {
    float v0 = a0 * (KS - 1), v1 = a1 * (KS - 1);
    int k0 = (int)floorf(v0); k0 = min(max(k0, 0), KS - 2);
    int k1 = (int)floorf(v1); k1 = min(max(k1, 0), KS - 2);
    float f0 = v0 - (float)k0, f1 = v1 - (float)k1;
    float g0 = 1.f - f0, g1 = 1.f - f1;
    wi0 = k0 + KS * k1;
    bw[0] = g0 * g1;
    bw[1] = f0 * g1;
    bw[2] = g0 * f1;
    bw[3] = f0 * f1;
}

// ---------------- edge pass 1 + fused S-zero + W2f prep ----------------
__global__ void k_edge1(const float* __restrict__ x, const float* __restrict__ ea,
                        const int* __restrict__ src, const int* __restrict__ dst,
                        const float* __restrict__ W2, const float* __restrict__ root2,
                        int E, int N) {
    if (blockIdx.x < ZB) {
        // W2f fragment prep (first 56 blocks; runs before gemm reads it)
        if (blockIdx.x < 56) {
            int t = blockIdx.x * 256 + threadIdx.x;
            int lane = t & 31, ng = (t >> 5) & 7, sg = t >> 8;
            int gid = lane >> 2, tig = lane & 3;
            int n = ng * 8 + gid;
            int k = sg * 16 + tig * 2;
            float f0 = 0.f, f1 = 0.f, f2 = 0.f, f3 = 0.f;
            if (sg < 50) {
                f0 = W2[k * C2 + n];       f1 = W2[(k + 1) * C2 + n];
                f2 = W2[(k + 8) * C2 + n]; f3 = W2[(k + 9) * C2 + n];
            } else if (sg >= 52 && sg < 54) {
                int kr = k - 832;
                f0 = root2[kr * C2 + n];       f1 = root2[(kr + 1) * C2 + n];
                f2 = root2[(kr + 8) * C2 + n]; f3 = root2[(kr + 9) * C2 + n];
            }
            __nv_bfloat162 lo = __float22bfloat162_rn(make_float2(f0, f1));
            __nv_bfloat162 hi = __float22bfloat162_rn(make_float2(f2, f3));
            g_W2f[t] = make_uint2(*(uint32_t*)&lo, *(uint32_t*)&hi);
        }
        // zero a slice of S (DRAM-bound; rides alongside atomic-bound edge work)
        long total4 = (long)N * 100;                   // uint4 count
        long per = (total4 + ZB - 1) / ZB;
        long base = (long)blockIdx.x * per;
        long end = min(base + per, total4);
        uint4* S4 = (uint4*)g_Sb;
        uint4 z4 = make_uint4(0u, 0u, 0u, 0u);
        for (long i = base + threadIdx.x; i < end; i += blockDim.x) S4[i] = z4;
        return;
    }
    int e = (blockIdx.x - ZB) * blockDim.x + threadIdx.x;
    if (e >= E) return;
    int wi0; float bw[4];
    float2 eav = ((const float2*)ea)[e];
    basis2w(eav.x, eav.y, wi0, bw);
    int s = src[e];
    float xs = x[s];
    int d = dst[e];
    float* Tp = g_T + d * K2 + wi0;
    atomicAdd(Tp,     bw[0] * xs);
    atomicAdd(Tp + 1, bw[1] * xs);
    atomicAdd(Tp + 5, bw[2] * xs);
    atomicAdd(Tp + 6, bw[3] * xs);
    atomicAdd(g_deg + d, 1.f);
    __nv_bfloat162 c01 = __float22bfloat162_rn(make_float2(bw[0], bw[1]));
    __nv_bfloat162 c23 = __float22bfloat162_rn(make_float2(bw[2], bw[3]));
    g_rec[e] = make_uint4((uint32_t)s | ((uint32_t)wi0 << 20), (uint32_t)d,
                          *(uint32_t*)&c01, *(uint32_t*)&c23);
}

// ---------------- layer-1 node update (per-thread form, atomic-free) ----------------
__global__ void k_h1(const float* __restrict__ x, const float* __restrict__ W1,
                     const float* __restrict__ root1, const float* __restrict__ b1, int N) {
    int t = blockIdx.x * blockDim.x + threadIdx.x;
    if (t >= N * 16) return;
    int n = t >> 4, c2 = t & 15;
    const float* Tp = g_T + n * K2;
    float a0 = 0.f, a1 = 0.f;
#pragma unroll
    for (int w = 0; w < K2; w++) {
        float tv = Tp[w];
        a0 += tv * W1[w * C1 + 2 * c2];
        a1 += tv * W1[w * C1 + 2 * c2 + 1];
    }
    float dinv = 1.f / fmaxf(g_deg[n], 1.f);
    float xn = x[n];
    float h0 = fmaxf(a0 * dinv + xn * root1[2 * c2]     + b1[2 * c2],     0.f);
    float h1 = fmaxf(a1 * dinv + xn * root1[2 * c2 + 1] + b1[2 * c2 + 1], 0.f);
    __nv_bfloat162 hb = __float22bfloat162_rn(make_float2(h0, h1));
    g_h1b[t] = *(unsigned int*)&hb;
    if (c2 == 0) g_dinv[n] = dinv;
}

// ---------------- edge pass 2: 16 lanes/edge, 16B record + h1 gather ----------------
__global__ void k_edge2(int E) {
    int gt = blockIdx.x * blockDim.x + threadIdx.x;
    int lane = gt & 31;
    int warp = gt >> 5;
    int e = warp * 2 + (lane >> 4);
    int hl = lane & 15;
    if (e >= E) return;
    uint4 r = g_rec[e];
    int s   = (int)(r.x & 0xFFFFFu);
    int wi0 = (int)(r.x >> 20);
    int d   = (int)r.y;
    float2 bw01 = __bfloat1622float2(*(__nv_bfloat162*)&r.z);
    float2 bw23 = __bfloat1622float2(*(__nv_bfloat162*)&r.w);
    float2 h = __bfloat1622float2(*(__nv_bfloat162*)&g_h1b[s * 16 + hl]);
    unsigned int* base = g_Sb + d * 400 + wi0 * 16 + hl;
    {
        __nv_bfloat162 v = __float22bfloat162_rn(make_float2(bw01.x * h.x, bw01.x * h.y));
        red_bf162(base, *(unsigned int*)&v);
    }
    {
        __nv_bfloat162 v = __float22bfloat162_rn(make_float2(bw01.y * h.x, bw01.y * h.y));
        red_bf162(base + 16, *(unsigned int*)&v);
    }
    {
        __nv_bfloat162 v = __float22bfloat162_rn(make_float2(bw23.x * h.x, bw23.x * h.y));
        red_bf162(base + 80, *(unsigned int*)&v);
    }
    {
        __nv_bfloat162 v = __float22bfloat162_rn(make_float2(bw23.y * h.x, bw23.y * h.y));
        red_bf162(base + 96, *(unsigned int*)&v);
    }
}

// ---------------- fused GEMM (HMMA) + dinv scale + epilogue + pooling + T/deg tail-zero ----------------
__global__ void __launch_bounds__(256) k_gemm_mma(const float* __restrict__ b2,
                                                  const int* __restrict__ batch, int N) {
    __shared__ __align__(16) uint8_t smA[16384];
    int tid = threadIdx.x;
    int warp = tid >> 5, lane = tid & 31;
    int gid = lane >> 2, tig = lane & 3;
    int rowBase = blockIdx.x * 128;
    uint32_t smA_b = smem_u32(smA);

    int rowA[4], chA[4], stoff[4];
    bool inb[4];
#pragma unroll
    for (int j = 0; j < 4; j++) {
        int c = tid + 256 * j;
        rowA[j] = c >> 3; chA[j] = c & 7;
        stoff[j] = rowA[j] * 128 + ((chA[j] ^ (rowA[j] & 7)) << 4);
        inb[j] = (rowBase + rowA[j]) < N;
    }

    float acc[8][4];
#pragma unroll
    for (int g = 0; g < 8; g++)
#pragma unroll
        for (int j = 0; j < 4; j++) acc[g][j] = 0.f;

    int r0 = rowBase + warp * 16 + gid;
    int r1 = r0 + 8;

    uint4 v[4];
#pragma unroll
    for (int j = 0; j < 4; j++) {
        v[j] = make_uint4(0u, 0u, 0u, 0u);
        if (inb[j])
            v[j] = *(const uint4*)(g_Sb + (rowBase + rowA[j]) * 400 + chA[j] * 4);
    }

    for (int c0 = 0; c0 < 14; c0++) {
#pragma unroll
        for (int j = 0; j < 4; j++) *(uint4*)(smA + stoff[j]) = v[j];
        __syncthreads();
        if (c0 < 13) {
            int cn = c0 + 1;
#pragma unroll
            for (int j = 0; j < 4; j++) {
                v[j] = make_uint4(0u, 0u, 0u, 0u);
                if (inb[j]) {
                    if (cn < 13) {
                        int off = cn * 32 + chA[j] * 4;
                        if (off < 400)
                            v[j] = *(const uint4*)(g_Sb + (rowBase + rowA[j]) * 400 + off);
                    } else if (chA[j] < 4) {
                        v[j] = *(const uint4*)(g_h1b + (rowBase + rowA[j]) * 16 + chA[j] * 4);
                    }
                }
            }
        }
#pragma unroll
        for (int ks = 0; ks < 4; ks++) {
            int mrow = warp * 16 + (lane & 15);
            uint32_t addr = smA_b + mrow * 128 + (((ks * 2 + (lane >> 4)) ^ (mrow & 7)) << 4);
            uint32_t a0, a1, a2, a3;
            ldmatrix_x4(a0, a1, a2, a3, addr);
            int sg = c0 * 4 + ks;
            const uint2* bf = g_W2f + (sg << 8) + lane;
#pragma unroll
            for (int ng = 0; ng < 8; ng++) {
                uint2 b = bf[ng << 5];
                mma_bf16(acc[ng], a0, a1, a2, a3, b.x, b.y);
            }
        }
        if (c0 == 12) {
            float di0 = (r0 < N) ? g_dinv[r0] : 0.f;
            float di1 = (r1 < N) ? g_dinv[r1] : 0.f;
#pragma unroll
            for (int ng = 0; ng < 8; ng++) {
                acc[ng][0] *= di0; acc[ng][1] *= di0;
                acc[ng][2] *= di1; acc[ng][3] *= di1;
            }
        }
        __syncthreads();
    }

    int bt0 = (r0 < N) ? batch[r0] : -1;
    int bt1 = (r1 < N) ? batch[r1] : -1;
#pragma unroll
    for (int ng = 0; ng < 8; ng++) {
        int col = ng * 8 + tig * 2;
        float2 bb = *(const float2*)(b2 + col);
        if (bt0 >= 0) {
            red_f32(g_pool + bt0 * C2 + col,     fmaxf(acc[ng][0] + bb.x, 0.f));
            red_f32(g_pool + bt0 * C2 + col + 1, fmaxf(acc[ng][1] + bb.y, 0.f));
        }
        if (bt1 >= 0) {
            red_f32(g_pool + bt1 * C2 + col,     fmaxf(acc[ng][2] + bb.x, 0.f));
            red_f32(g_pool + bt1 * C2 + col + 1, fmaxf(acc[ng][3] + bb.y, 0.f));
        }
    }

    // tail: zero T/deg for the next call (T/deg already consumed by h1 this call)
    int ztid = blockIdx.x * 256 + tid;
    int zstride = gridDim.x * 256;
    for (int i = ztid; i < N * K2; i += zstride) g_T[i] = 0.f;
    for (int i = ztid; i < N; i += zstride) g_deg[i] = 0.f;
}

// ---------------- head MLP + log_softmax + pool tail-zero ----------------
__global__ void k_mlp(const float* __restrict__ Wf1, const float* __restrict__ bf1,
                      const float* __restrict__ Wf2, const float* __restrict__ bf2,
                      const int* __restrict__ batch, int N,
                      float* __restrict__ out) {
    int b = blockIdx.x;
    int j = threadIdx.x;
    __shared__ float gs[C2];
    __shared__ float ts[128];
    __shared__ float lg[10];
    __shared__ float s_cinv;
    if (j == 0) {
        int lo = 0, hi = N;
        while (lo < hi) { int m = (lo + hi) >> 1; if (batch[m] < b) lo = m + 1; else hi = m; }
        int lo2 = lo; hi = N;
        while (lo2 < hi) { int m = (lo2 + hi) >> 1; if (batch[m] < b + 1) lo2 = m + 1; else hi = m; }
        s_cinv = 1.f / fmaxf((float)(lo2 - lo), 1.f);
    }
    __syncthreads();
    if (j < C2) gs[j] = g_pool[b * C2 + j] * s_cinv;
    __syncthreads();
    if (j < C2) g_pool[b * C2 + j] = 0.f;   // tail-zero for next call (gs already staged)
    float t = bf1[j];
#pragma unroll
    for (int k = 0; k < C2; k++) t += gs[k] * Wf1[k * 128 + j];
    ts[j] = fmaxf(t, 0.f);
    __syncthreads();
    if (j < 10) {
        float a = bf2[j];
#pragma unroll
        for (int q = 0; q < 128; q++) a += ts[q] * Wf2[q * 10 + j];
        lg[j] = a;
    }
    __syncthreads();
    if (j == 0) {
        float m = lg[0];
#pragma unroll
        for (int q = 1; q < 10; q++) m = fmaxf(m, lg[q]);
        float s = 0.f;
#pragma unroll
        for (int q = 0; q < 10; q++) s += expf(lg[q] - m);
        float l = logf(s) + m;
#pragma unroll
        for (int q = 0; q < 10; q++) out[b * 10 + q] = lg[q] - l;
    }
}

// ---------------- launch ----------------
extern "C" void kernel_launch(void* const* d_in, const int* in_sizes, int n_in,
                              void* d_out, int out_size) {
    const float* x     = (const float*)d_in[0];
    const float* ea    = (const float*)d_in[1];
    const float* W1    = (const float*)d_in[2];
    const float* root1 = (const float*)d_in[3];
    const float* b1    = (const float*)d_in[4];
    const float* W2    = (const float*)d_in[5];
    const float* root2 = (const float*)d_in[6];
    const float* b2    = (const float*)d_in[7];
    const float* Wf1   = (const float*)d_in[8];
    const float* bf1   = (const float*)d_in[9];
    const float* Wf2   = (const float*)d_in[10];
    const float* bf2   = (const float*)d_in[11];
    const int*   ei    = (const int*)d_in[12];
    const int*   batch = (const int*)d_in[13];

    int N = in_sizes[0];
    int E = in_sizes[1] / 2;
    const int* src = ei;
    const int* dst = ei + E;
    float* out = (float*)d_out;

    k_edge1<<<ZB + (E + 255) / 256, 256>>>(x, ea, src, dst, W2, root2, E, N);
    k_h1<<<(N * 16 + 255) / 256, 256>>>(x, W1, root1, b1, N);
    k_edge2<<<(E * 16 + 255) / 256, 256>>>(E);
    k_gemm_mma<<<(N + 127) / 128, 256>>>(b2, batch, N);
    k_mlp<<<NG, 128>>>(Wf1, bf1, Wf2, bf2, batch, N, out);
}